// round 4
// baseline (speedup 1.0000x reference)
#include <cuda_runtime.h>

#define NN 50000
#define EE 1600000

// ---------------- scratch (device globals; zero-initialized at load) -------
__device__ float g_h[NN * 64];      // GEMM output (per-layer features)
__device__ float g_agg[NN * 64];    // GAT aggregation output (pre-BN)
__device__ float g_asrc[NN * 4];
__device__ float g_adst[NN * 4];
__device__ int   g_rowptr[NN + 1];
__device__ int   g_cursor[NN];      // INVARIANT: zeroed by k_alpha4 before k_count
__device__ int   g_srcs[EE];        // CSR columns (no self slots; self handled analytically)
__device__ float g_stat[256];       // [0:64) sum [64:128) sumsq (zero at entry; restored
                                    // by k_bnfinal), [128:192) scale, [192:256) shift

__device__ __forceinline__ float neg_inf() { return __int_as_float(0xff800000); }

// ---------------- CSR build -------------------------------------------------
__global__ void k_count(const int* __restrict__ ei) {
    int e = blockIdx.x * blockDim.x + threadIdx.x;
    if (e < EE) atomicAdd(&g_cursor[ei[EE + e]], 1);
}

__global__ void k_scan() {
    __shared__ int part[1024];
    const int t = threadIdx.x;
    const int CH = (NN + 1023) / 1024;
    const int start = t * CH;
    int sum = 0;
    for (int i = 0; i < CH; i++) {
        int v = start + i;
        if (v < NN) sum += g_cursor[v];
    }
    part[t] = sum;
    __syncthreads();
    for (int off = 1; off < 1024; off <<= 1) {
        int v = (t >= off) ? part[t - off] : 0;
        __syncthreads();
        part[t] += v;
        __syncthreads();
    }
    int run = (t > 0) ? part[t - 1] : 0;
    for (int i = 0; i < CH; i++) {
        int v = start + i;
        if (v < NN) {
            int d = g_cursor[v];
            g_rowptr[v] = run;
            g_cursor[v] = run;  // scatter cursor starts at row begin
            run += d;
        }
    }
    if (t == 1023) g_rowptr[NN] = part[1023];
}

__global__ void k_scatter(const int* __restrict__ ei) {
    int e = blockIdx.x * blockDim.x + threadIdx.x;
    if (e < EE) {
        int s = ei[e];
        int d = ei[EE + e];
        int pos = atomicAdd(&g_cursor[d], 1);
        g_srcs[pos] = s;
    }
}

// ---------------- SGEMM: C[M,NO] = A'[M,K] * W[K,NO]; A' = BN+ReLU(A) opt. --
template <int K, int NO, bool BN>
__global__ __launch_bounds__(256) void k_gemm(const float* __restrict__ A,
                                              const float* __restrict__ W,
                                              float* __restrict__ C) {
    __shared__ float As[64][36];
    __shared__ float Ws[32][64];
    const int tid = threadIdx.x;
    const int ty = tid >> 4;
    const int tx = tid & 15;
    const int m0 = blockIdx.x * 64;
    const int lr = tid >> 3;
    const int lc = (tid & 7) * 4;
    float acc[4][4] = {};

    for (int kt = 0; kt < K; kt += 32) {
        float4 sc, sh;
        if (BN) {
            sc = *reinterpret_cast<const float4*>(&g_stat[128 + kt + lc]);
            sh = *reinterpret_cast<const float4*>(&g_stat[192 + kt + lc]);
        }
#pragma unroll
        for (int rr = 0; rr < 64; rr += 32) {
            int row = m0 + lr + rr;
            float4 v = make_float4(0.f, 0.f, 0.f, 0.f);
            if (row < NN)
                v = *reinterpret_cast<const float4*>(A + (size_t)row * K + kt + lc);
            if (BN) {
                v.x = fmaxf(v.x * sc.x + sh.x, 0.f);
                v.y = fmaxf(v.y * sc.y + sh.y, 0.f);
                v.z = fmaxf(v.z * sc.z + sh.z, 0.f);
                v.w = fmaxf(v.w * sc.w + sh.w, 0.f);
            }
            *reinterpret_cast<float4*>(&As[lr + rr][lc]) = v;
        }
#pragma unroll
        for (int kk = 0; kk < 32; kk += 16) {
            int k = ty + kk;
            int c = tx * 4;
            float4 v = make_float4(0.f, 0.f, 0.f, 0.f);
            if (NO == 64 || c < NO)
                v = *reinterpret_cast<const float4*>(W + (size_t)(kt + k) * NO + c);
            *reinterpret_cast<float4*>(&Ws[k][c]) = v;
        }
        __syncthreads();
#pragma unroll
        for (int k = 0; k < 32; k++) {
            float a0 = As[ty * 4 + 0][k];
            float a1 = As[ty * 4 + 1][k];
            float a2 = As[ty * 4 + 2][k];
            float a3 = As[ty * 4 + 3][k];
            float4 b = *reinterpret_cast<const float4*>(&Ws[k][tx * 4]);
            acc[0][0] += a0 * b.x; acc[0][1] += a0 * b.y; acc[0][2] += a0 * b.z; acc[0][3] += a0 * b.w;
            acc[1][0] += a1 * b.x; acc[1][1] += a1 * b.y; acc[1][2] += a1 * b.z; acc[1][3] += a1 * b.w;
            acc[2][0] += a2 * b.x; acc[2][1] += a2 * b.y; acc[2][2] += a2 * b.z; acc[2][3] += a2 * b.w;
            acc[3][0] += a3 * b.x; acc[3][1] += a3 * b.y; acc[3][2] += a3 * b.z; acc[3][3] += a3 * b.w;
        }
        __syncthreads();
    }
#pragma unroll
    for (int i = 0; i < 4; i++) {
        int row = m0 + ty * 4 + i;
        if (row < NN && (NO == 64 || tx * 4 < NO)) {
            float4 v = make_float4(acc[i][0], acc[i][1], acc[i][2], acc[i][3]);
            *reinterpret_cast<float4*>(C + (size_t)row * NO + tx * 4) = v;
        }
    }
}

// ---------------- per-node attention coefficients ---------------------------
// Also restores the cursor-zero invariant (runs between k_scatter uses).
__global__ void k_alpha4(const float* __restrict__ h, const float* __restrict__ as,
                         const float* __restrict__ ad) {
    int gw = (blockIdx.x * blockDim.x + threadIdx.x) >> 5;
    int lane = threadIdx.x & 31;
    if (gw >= NN) return;
    float h0 = h[(size_t)gw * 64 + lane];
    float h1 = h[(size_t)gw * 64 + lane + 32];
    float s0 = h0 * as[lane];
    float s1 = h1 * as[lane + 32];
    float d0 = h0 * ad[lane];
    float d1 = h1 * ad[lane + 32];
#pragma unroll
    for (int off = 8; off; off >>= 1) {
        s0 += __shfl_xor_sync(0xffffffffu, s0, off);
        s1 += __shfl_xor_sync(0xffffffffu, s1, off);
        d0 += __shfl_xor_sync(0xffffffffu, d0, off);
        d1 += __shfl_xor_sync(0xffffffffu, d1, off);
    }
    if ((lane & 15) == 0) {
        int g = lane >> 4;
        g_asrc[gw * 4 + g] = s0;
        g_asrc[gw * 4 + g + 2] = s1;
        g_adst[gw * 4 + g] = d0;
        g_adst[gw * 4 + g + 2] = d1;
    }
    if (lane == 0) g_cursor[gw] = 0;
}

__global__ void k_alpha1(const float* __restrict__ h, const float* __restrict__ as,
                         const float* __restrict__ ad) {
    int gw = (blockIdx.x * blockDim.x + threadIdx.x) >> 5;
    int lane = threadIdx.x & 31;
    if (gw >= NN) return;
    float s = 0.f, d = 0.f;
    if (lane < 40) {
        float hv = h[(size_t)gw * 40 + lane];
        s = hv * as[lane];
        d = hv * ad[lane];
    }
    if (lane < 8) {
        float hv = h[(size_t)gw * 40 + 32 + lane];
        s += hv * as[32 + lane];
        d += hv * ad[32 + lane];
    }
#pragma unroll
    for (int off = 16; off; off >>= 1) {
        s += __shfl_xor_sync(0xffffffffu, s, off);
        d += __shfl_xor_sync(0xffffffffu, d, off);
    }
    if (lane == 0) {
        g_asrc[gw] = s;
        g_adst[gw] = d;
    }
}

// ---------------- fused softmax+aggregate, H=4 C=16 (one warp per node) -----
// Weights computed inline (no shift: logits O(1)); self-loop analytic.
template <bool STATS>
__global__ __launch_bounds__(256) void k_agg4(const float* __restrict__ h,
                                              const float* __restrict__ bias,
                                              float* __restrict__ out) {
    __shared__ float sV[8][64];
    const int tid = threadIdx.x;
    const int wid = tid >> 5;
    const int lane = tid & 31;
    const int gw = (blockIdx.x * 256 + tid) >> 5;
    const bool valid = gw < NN;
    const int c0 = lane, c1 = lane + 32;
    const bool hi = lane >= 16;   // head of c0: hi?1:0; head of c1: hi?3:2
    float o0 = 0.f, o1 = 0.f;

    if (valid) {
        const int r0 = g_rowptr[gw];
        const int r1 = g_rowptr[gw + 1];
        const float4 ad = *reinterpret_cast<const float4*>(&g_adst[gw * 4]);
        const float4 asl = *reinterpret_cast<const float4*>(&g_asrc[gw * 4]);
        float e;
        float4 wsv;
        e = asl.x + ad.x; e = fmaxf(e, 0.2f * e); wsv.x = __expf(e);
        e = asl.y + ad.y; e = fmaxf(e, 0.2f * e); wsv.y = __expf(e);
        e = asl.z + ad.z; e = fmaxf(e, 0.2f * e); wsv.z = __expf(e);
        e = asl.w + ad.w; e = fmaxf(e, 0.2f * e); wsv.w = __expf(e);
        float w0 = hi ? wsv.y : wsv.x;
        float w1 = hi ? wsv.w : wsv.z;
        float acc0 = w0 * h[(size_t)gw * 64 + c0];
        float acc1 = w1 * h[(size_t)gw * 64 + c1];
        float ss0 = w0, ss1 = w1;

        for (int base = r0; base < r1; base += 8) {
            int n = r1 - base; if (n > 8) n = 8;
            int sj = (lane < n) ? g_srcs[base + lane] : 0;
            float4 av = make_float4(0.f, 0.f, 0.f, 0.f);
            if (lane < n) av = *reinterpret_cast<const float4*>(&g_asrc[sj * 4]);
            float4 wv;
            e = av.x + ad.x; e = fmaxf(e, 0.2f * e); wv.x = __expf(e);
            e = av.y + ad.y; e = fmaxf(e, 0.2f * e); wv.y = __expf(e);
            e = av.z + ad.z; e = fmaxf(e, 0.2f * e); wv.z = __expf(e);
            e = av.w + ad.w; e = fmaxf(e, 0.2f * e); wv.w = __expf(e);
#pragma unroll
            for (int j = 0; j < 8; j++) {
                if (j < n) {
                    int s = __shfl_sync(0xffffffffu, sj, j);
                    float wx = __shfl_sync(0xffffffffu, wv.x, j);
                    float wy = __shfl_sync(0xffffffffu, wv.y, j);
                    float wz = __shfl_sync(0xffffffffu, wv.z, j);
                    float ww = __shfl_sync(0xffffffffu, wv.w, j);
                    float w0e = hi ? wy : wx;
                    float w1e = hi ? ww : wz;
                    acc0 += w0e * h[(size_t)s * 64 + c0];
                    acc1 += w1e * h[(size_t)s * 64 + c1];
                    ss0 += w0e;
                    ss1 += w1e;
                }
            }
        }
        o0 = acc0 / (ss0 + 1e-16f) + bias[c0];
        o1 = acc1 / (ss1 + 1e-16f) + bias[c1];
        out[(size_t)gw * 64 + c0] = o0;
        out[(size_t)gw * 64 + c1] = o1;
    }
    if (STATS) {
        sV[wid][c0] = valid ? o0 : 0.f;
        sV[wid][c1] = valid ? o1 : 0.f;
        __syncthreads();
        if (tid < 64) {
            float s = 0.f, q = 0.f;
#pragma unroll
            for (int w = 0; w < 8; w++) {
                float v = sV[w][tid];
                s += v;
                q += v * v;
            }
            atomicAdd(&g_stat[tid], s);
            atomicAdd(&g_stat[64 + tid], q);
        }
    }
}

// ---------------- fused aggregate H=1 C=40 + bias + log_softmax -------------
__global__ __launch_bounds__(256) void k_agg1_lsm(const float* __restrict__ h,
                                                  const float* __restrict__ bias,
                                                  float* __restrict__ out) {
    int gw = (blockIdx.x * blockDim.x + threadIdx.x) >> 5;
    int lane = threadIdx.x & 31;
    if (gw >= NN) return;
    const int r0 = g_rowptr[gw];
    const int r1 = g_rowptr[gw + 1];
    const int c0 = lane, c1 = lane + 32;
    const bool use1 = lane < 8;
    const float ad = g_adst[gw];

    float e = g_asrc[gw] + ad;
    e = fmaxf(e, 0.2f * e);
    float ws = __expf(e);
    float acc0 = ws * h[(size_t)gw * 40 + c0];
    float acc1 = use1 ? ws * h[(size_t)gw * 40 + c1] : 0.f;
    float ss = ws;

    for (int base = r0; base < r1; base += 8) {
        int n = r1 - base; if (n > 8) n = 8;
        int sj = (lane < n) ? g_srcs[base + lane] : 0;
        float av = (lane < n) ? g_asrc[sj] : 0.f;
        float ee = av + ad;
        ee = fmaxf(ee, 0.2f * ee);
        float wv = __expf(ee);
#pragma unroll
        for (int j = 0; j < 8; j++) {
            if (j < n) {
                int s = __shfl_sync(0xffffffffu, sj, j);
                float w = __shfl_sync(0xffffffffu, wv, j);
                acc0 += w * h[(size_t)s * 40 + c0];
                if (use1) acc1 += w * h[(size_t)s * 40 + c1];
                ss += w;
            }
        }
    }
    float inv = 1.f / (ss + 1e-16f);
    float o0 = acc0 * inv + bias[c0];
    float o1 = use1 ? (acc1 * inv + bias[c1]) : neg_inf();
    float m = fmaxf(o0, o1);
#pragma unroll
    for (int off = 16; off; off >>= 1) m = fmaxf(m, __shfl_xor_sync(0xffffffffu, m, off));
    float se = __expf(o0 - m) + (use1 ? __expf(o1 - m) : 0.f);
#pragma unroll
    for (int off = 16; off; off >>= 1) se += __shfl_xor_sync(0xffffffffu, se, off);
    float ls = __logf(se);
    out[(size_t)gw * 40 + c0] = o0 - m - ls;
    if (use1) out[(size_t)gw * 40 + c1] = o1 - m - ls;
}

// ---------------- BN finalize (also restores zero-sum invariant) ------------
__global__ void k_bnfinal(const float* __restrict__ g, const float* __restrict__ beta) {
    int c = threadIdx.x;
    if (c >= 64) return;
    float mean = g_stat[c] * (1.0f / NN);
    float var = g_stat[64 + c] * (1.0f / NN) - mean * mean;
    float sc = g[c] * rsqrtf(var + 1e-5f);
    g_stat[128 + c] = sc;
    g_stat[192 + c] = beta[c] - mean * sc;
    g_stat[c] = 0.f;
    g_stat[64 + c] = 0.f;
}

// ---------------- launch ----------------------------------------------------
extern "C" void kernel_launch(void* const* d_in, const int* in_sizes, int n_in,
                              void* d_out, int out_size) {
    const float* x   = (const float*)d_in[0];
    const int*   ei  = (const int*)d_in[1];
    const float* W0  = (const float*)d_in[2];
    const float* as0 = (const float*)d_in[3];
    const float* ad0 = (const float*)d_in[4];
    const float* b0  = (const float*)d_in[5];
    const float* g0  = (const float*)d_in[6];
    const float* be0 = (const float*)d_in[7];
    const float* W1  = (const float*)d_in[8];
    const float* as1 = (const float*)d_in[9];
    const float* ad1 = (const float*)d_in[10];
    const float* b1  = (const float*)d_in[11];
    const float* g1  = (const float*)d_in[12];
    const float* be1 = (const float*)d_in[13];
    const float* W2  = (const float*)d_in[14];
    const float* as2 = (const float*)d_in[15];
    const float* ad2 = (const float*)d_in[16];
    const float* b2  = (const float*)d_in[17];
    float* out = (float*)d_out;

    const int gemmGrid = (NN + 63) / 64;
    const int nodeWarpGrid = (NN + 7) / 8;

    k_gemm<128, 64, false><<<gemmGrid, 256>>>(x, W0, g_h);   // 1
    k_alpha4<<<nodeWarpGrid, 256>>>(g_h, as0, ad0);          // 2 (zeros cursor)
    k_count<<<(EE + 255) / 256, 256>>>(ei);                  // 3
    k_scan<<<1, 1024>>>();                                   // 4  <- profile slot
    k_scatter<<<(EE + 255) / 256, 256>>>(ei);                // 5

    // ---- layer 0 (agg run twice: probe measures its true cost via dur delta)
    k_agg4<false><<<nodeWarpGrid, 256>>>(g_h, b0, g_agg);    // 6 probe
    k_agg4<true><<<nodeWarpGrid, 256>>>(g_h, b0, g_agg);     // 7
    k_bnfinal<<<1, 64>>>(g0, be0);                           // 8

    // ---- layer 1 ----
    k_gemm<64, 64, true><<<gemmGrid, 256>>>(g_agg, W1, g_h); // 9
    k_alpha4<<<nodeWarpGrid, 256>>>(g_h, as1, ad1);          // 10
    k_agg4<true><<<nodeWarpGrid, 256>>>(g_h, b1, g_agg);     // 11
    k_bnfinal<<<1, 64>>>(g1, be1);                           // 12

    // ---- layer 2 ----
    k_gemm<64, 40, true><<<gemmGrid, 256>>>(g_agg, W2, g_h); // 13
    k_alpha1<<<nodeWarpGrid, 256>>>(g_h, as2, ad2);          // 14
    k_agg1_lsm<<<nodeWarpGrid, 256>>>(g_h, b2, out);         // 15
}

// round 5
// speedup vs baseline: 1.4076x; 1.4076x over previous
#include <cuda_runtime.h>

#define NN 50000
#define EE 1600000

// ---------------- scratch (device globals; zero-initialized at load) -------
__device__ float g_h[NN * 64];      // GEMM output (per-layer features)
__device__ float g_agg[NN * 64];    // GAT aggregation output (pre-BN)
__device__ float g_asrc[NN * 4];
__device__ float g_adst[NN * 4];
__device__ float g_w[(size_t)EE * 4];  // per-edge per-head softmax numerators
__device__ float g_sum[NN * 4];        // per-node per-head denominators (incl. self)
__device__ int   g_rowptr[NN + 1];
__device__ int   g_cursor[NN];      // INVARIANT: zero at kernel_launch entry
__device__ int   g_srcs[EE];        // CSR columns (self-loop handled analytically)
__device__ float g_stat[256];       // [0:64) sum [64:128) sumsq (zero at entry; restored
                                    // by k_bnfinal), [128:192) scale, [192:256) shift

__device__ __forceinline__ float neg_inf() { return __int_as_float(0xff800000); }
__device__ __forceinline__ float lrelu(float e) { return fmaxf(e, 0.2f * e); }

// ---------------- CSR build -------------------------------------------------
__global__ void k_count(const int* __restrict__ ei) {
    int e = blockIdx.x * blockDim.x + threadIdx.x;
    if (e < EE) atomicAdd(&g_cursor[ei[EE + e]], 1);
}

__global__ void k_scan() {
    __shared__ int part[1024];
    const int t = threadIdx.x;
    const int CH = (NN + 1023) / 1024;
    const int start = t * CH;
    int sum = 0;
    for (int i = 0; i < CH; i++) {
        int v = start + i;
        if (v < NN) sum += g_cursor[v];
    }
    part[t] = sum;
    __syncthreads();
    for (int off = 1; off < 1024; off <<= 1) {
        int v = (t >= off) ? part[t - off] : 0;
        __syncthreads();
        part[t] += v;
        __syncthreads();
    }
    int run = (t > 0) ? part[t - 1] : 0;
    for (int i = 0; i < CH; i++) {
        int v = start + i;
        if (v < NN) {
            int d = g_cursor[v];
            g_rowptr[v] = run;
            g_cursor[v] = run;
            run += d;
        }
    }
    if (t == 1023) g_rowptr[NN] = part[1023];
}

__global__ void k_scatter(const int* __restrict__ ei) {
    int e = blockIdx.x * blockDim.x + threadIdx.x;
    if (e < EE) {
        int s = ei[e];
        int d = ei[EE + e];
        int pos = atomicAdd(&g_cursor[d], 1);
        g_srcs[pos] = s;
    }
}

// ---------------- SGEMM + fused alpha epilogue ------------------------------
// C[M,NO] = A'[M,K] * W[K,NO]; A' = BN+ReLU(A) if BN.
// Epilogue: g_asrc/g_adst[row,(H)] = sum_c h[row,c] * a_{s,d}[c] per head.
template <int K, int NO, bool BN, int H>
__global__ __launch_bounds__(256) void k_gemm(const float* __restrict__ A,
                                              const float* __restrict__ W,
                                              float* __restrict__ C,
                                              const float* __restrict__ a_s,
                                              const float* __restrict__ a_d) {
    __shared__ float As[64][36];
    __shared__ float Ws[32][64];
    const int tid = threadIdx.x;
    const int ty = tid >> 4;
    const int tx = tid & 15;
    const int m0 = blockIdx.x * 64;
    const int lr = tid >> 3;
    const int lc = (tid & 7) * 4;
    float acc[4][4] = {};

    for (int kt = 0; kt < K; kt += 32) {
        float4 sc, sh;
        if (BN) {
            sc = *reinterpret_cast<const float4*>(&g_stat[128 + kt + lc]);
            sh = *reinterpret_cast<const float4*>(&g_stat[192 + kt + lc]);
        }
#pragma unroll
        for (int rr = 0; rr < 64; rr += 32) {
            int row = m0 + lr + rr;
            float4 v = make_float4(0.f, 0.f, 0.f, 0.f);
            if (row < NN)
                v = *reinterpret_cast<const float4*>(A + (size_t)row * K + kt + lc);
            if (BN) {
                v.x = fmaxf(v.x * sc.x + sh.x, 0.f);
                v.y = fmaxf(v.y * sc.y + sh.y, 0.f);
                v.z = fmaxf(v.z * sc.z + sh.z, 0.f);
                v.w = fmaxf(v.w * sc.w + sh.w, 0.f);
            }
            *reinterpret_cast<float4*>(&As[lr + rr][lc]) = v;
        }
#pragma unroll
        for (int kk = 0; kk < 32; kk += 16) {
            int k = ty + kk;
            int c = tx * 4;
            float4 v = make_float4(0.f, 0.f, 0.f, 0.f);
            if (NO == 64 || c < NO)
                v = *reinterpret_cast<const float4*>(W + (size_t)(kt + k) * NO + c);
            *reinterpret_cast<float4*>(&Ws[k][c]) = v;
        }
        __syncthreads();
#pragma unroll
        for (int k = 0; k < 32; k++) {
            float a0 = As[ty * 4 + 0][k];
            float a1 = As[ty * 4 + 1][k];
            float a2 = As[ty * 4 + 2][k];
            float a3 = As[ty * 4 + 3][k];
            float4 b = *reinterpret_cast<const float4*>(&Ws[k][tx * 4]);
            acc[0][0] += a0 * b.x; acc[0][1] += a0 * b.y; acc[0][2] += a0 * b.z; acc[0][3] += a0 * b.w;
            acc[1][0] += a1 * b.x; acc[1][1] += a1 * b.y; acc[1][2] += a1 * b.z; acc[1][3] += a1 * b.w;
            acc[2][0] += a2 * b.x; acc[2][1] += a2 * b.y; acc[2][2] += a2 * b.z; acc[2][3] += a2 * b.w;
            acc[3][0] += a3 * b.x; acc[3][1] += a3 * b.y; acc[3][2] += a3 * b.z; acc[3][3] += a3 * b.w;
        }
        __syncthreads();
    }
    // store C
#pragma unroll
    for (int i = 0; i < 4; i++) {
        int row = m0 + ty * 4 + i;
        if (row < NN && (NO == 64 || tx * 4 < NO)) {
            float4 v = make_float4(acc[i][0], acc[i][1], acc[i][2], acc[i][3]);
            *reinterpret_cast<float4*>(C + (size_t)row * NO + tx * 4) = v;
        }
    }
    // fused alpha epilogue
    const bool colok = (NO == 64) || (tx * 4 < NO);
    float4 av = make_float4(0.f, 0.f, 0.f, 0.f), dv = av;
    if (colok) {
        av = *reinterpret_cast<const float4*>(a_s + tx * 4);
        dv = *reinterpret_cast<const float4*>(a_d + tx * 4);
    }
#pragma unroll
    for (int i = 0; i < 4; i++) {
        float ps = acc[i][0] * av.x + acc[i][1] * av.y + acc[i][2] * av.z + acc[i][3] * av.w;
        float pd = acc[i][0] * dv.x + acc[i][1] * dv.y + acc[i][2] * dv.z + acc[i][3] * dv.w;
        if (H == 4) {
            ps += __shfl_xor_sync(0xffffffffu, ps, 1);
            pd += __shfl_xor_sync(0xffffffffu, pd, 1);
            ps += __shfl_xor_sync(0xffffffffu, ps, 2);
            pd += __shfl_xor_sync(0xffffffffu, pd, 2);
            int row = m0 + ty * 4 + i;
            if ((tx & 3) == 0 && row < NN) {
                g_asrc[row * 4 + (tx >> 2)] = ps;
                g_adst[row * 4 + (tx >> 2)] = pd;
            }
        } else {
            ps += __shfl_xor_sync(0xffffffffu, ps, 1);
            pd += __shfl_xor_sync(0xffffffffu, pd, 1);
            ps += __shfl_xor_sync(0xffffffffu, ps, 2);
            pd += __shfl_xor_sync(0xffffffffu, pd, 2);
            ps += __shfl_xor_sync(0xffffffffu, ps, 4);
            pd += __shfl_xor_sync(0xffffffffu, pd, 4);
            ps += __shfl_xor_sync(0xffffffffu, ps, 8);
            pd += __shfl_xor_sync(0xffffffffu, pd, 8);
            int row = m0 + ty * 4 + i;
            if (tx == 0 && row < NN) {
                g_asrc[row] = ps;
                g_adst[row] = pd;
            }
        }
    }
}

// ---------------- per-edge weights + per-node sums (lanes over edges) -------
__global__ __launch_bounds__(256) void k_wgt4() {
    int gw = (blockIdx.x * blockDim.x + threadIdx.x) >> 5;
    int lane = threadIdx.x & 31;
    if (gw >= NN) return;
    const int r0 = g_rowptr[gw];
    const int r1 = g_rowptr[gw + 1];
    const float4 ad = *reinterpret_cast<const float4*>(&g_adst[gw * 4]);
    float4 ss = make_float4(0.f, 0.f, 0.f, 0.f);
    for (int i = r0 + lane; i < r1; i += 32) {
        int s = g_srcs[i];
        float4 av = *reinterpret_cast<const float4*>(&g_asrc[s * 4]);
        float4 w;
        w.x = __expf(lrelu(av.x + ad.x));
        w.y = __expf(lrelu(av.y + ad.y));
        w.z = __expf(lrelu(av.z + ad.z));
        w.w = __expf(lrelu(av.w + ad.w));
        *reinterpret_cast<float4*>(&g_w[(size_t)i * 4]) = w;
        ss.x += w.x; ss.y += w.y; ss.z += w.z; ss.w += w.w;
    }
    if (lane == 0) {  // self-loop contribution to the denominator
        const float4 asl = *reinterpret_cast<const float4*>(&g_asrc[gw * 4]);
        ss.x += __expf(lrelu(asl.x + ad.x));
        ss.y += __expf(lrelu(asl.y + ad.y));
        ss.z += __expf(lrelu(asl.z + ad.z));
        ss.w += __expf(lrelu(asl.w + ad.w));
        g_cursor[gw] = 0;  // restore invariant for next launch's k_count
    }
#pragma unroll
    for (int off = 16; off; off >>= 1) {
        ss.x += __shfl_xor_sync(0xffffffffu, ss.x, off);
        ss.y += __shfl_xor_sync(0xffffffffu, ss.y, off);
        ss.z += __shfl_xor_sync(0xffffffffu, ss.z, off);
        ss.w += __shfl_xor_sync(0xffffffffu, ss.w, off);
    }
    if (lane == 0) *reinterpret_cast<float4*>(&g_sum[gw * 4]) = ss;
}

__global__ __launch_bounds__(256) void k_wgt1() {
    int gw = (blockIdx.x * blockDim.x + threadIdx.x) >> 5;
    int lane = threadIdx.x & 31;
    if (gw >= NN) return;
    const int r0 = g_rowptr[gw];
    const int r1 = g_rowptr[gw + 1];
    const float ad = g_adst[gw];
    float ss = 0.f;
    for (int i = r0 + lane; i < r1; i += 32) {
        float w = __expf(lrelu(g_asrc[g_srcs[i]] + ad));
        g_w[i] = w;
        ss += w;
    }
    if (lane == 0) ss += __expf(lrelu(g_asrc[gw] + ad));
#pragma unroll
    for (int off = 16; off; off >>= 1) ss += __shfl_xor_sync(0xffffffffu, ss, off);
    if (lane == 0) g_sum[gw] = ss;
}

// ---------------- gather-aggregate, H=4 C=16 --------------------------------
// NO shfl / NO predication in the hot loop: broadcast LDGs keep loads
// reorderable so ptxas batches 8 src + 16 h + 16 w loads (high MLP).
template <bool STATS>
__global__ __launch_bounds__(256) void k_agg4(const float* __restrict__ h,
                                              const float* __restrict__ bias,
                                              float* __restrict__ out) {
    __shared__ float sV[8][64];
    const int tid = threadIdx.x;
    const int wid = tid >> 5;
    const int lane = tid & 31;
    const int gw = (blockIdx.x * 256 + tid) >> 5;
    const bool valid = gw < NN;
    const int c0 = lane, c1 = lane + 32;
    const bool hi = lane >= 16;
    const int h0 = hi ? 1 : 0;
    const int h1 = hi ? 3 : 2;
    float o0 = 0.f, o1 = 0.f;

    if (valid) {
        const int r0 = g_rowptr[gw];
        const int r1 = g_rowptr[gw + 1];
        // analytic self-loop
        const float4 ad = *reinterpret_cast<const float4*>(&g_adst[gw * 4]);
        const float4 asl = *reinterpret_cast<const float4*>(&g_asrc[gw * 4]);
        float wsx = __expf(lrelu(asl.x + ad.x));
        float wsy = __expf(lrelu(asl.y + ad.y));
        float wsz = __expf(lrelu(asl.z + ad.z));
        float wsw = __expf(lrelu(asl.w + ad.w));
        float acc0 = (hi ? wsy : wsx) * h[(size_t)gw * 64 + c0];
        float acc1 = (hi ? wsw : wsz) * h[(size_t)gw * 64 + c1];

        int base = r0;
        for (; base + 8 <= r1; base += 8) {
            int s[8];
#pragma unroll
            for (int j = 0; j < 8; j++) s[j] = g_srcs[base + j];  // broadcast
            float w0[8], w1[8];
#pragma unroll
            for (int j = 0; j < 8; j++) {
                w0[j] = g_w[(size_t)(base + j) * 4 + h0];
                w1[j] = g_w[(size_t)(base + j) * 4 + h1];
            }
            float hv0[8], hv1[8];
#pragma unroll
            for (int j = 0; j < 8; j++) {
                hv0[j] = h[(size_t)s[j] * 64 + c0];
                hv1[j] = h[(size_t)s[j] * 64 + c1];
            }
#pragma unroll
            for (int j = 0; j < 8; j++) {
                acc0 += w0[j] * hv0[j];
                acc1 += w1[j] * hv1[j];
            }
        }
        for (int i = base; i < r1; i++) {  // remainder (<8), still shfl-free
            int s = g_srcs[i];
            acc0 += g_w[(size_t)i * 4 + h0] * h[(size_t)s * 64 + c0];
            acc1 += g_w[(size_t)i * 4 + h1] * h[(size_t)s * 64 + c1];
        }
        float4 sm = *reinterpret_cast<const float4*>(&g_sum[gw * 4]);
        float s0 = hi ? sm.y : sm.x;
        float s1 = hi ? sm.w : sm.z;
        o0 = acc0 / (s0 + 1e-16f) + bias[c0];
        o1 = acc1 / (s1 + 1e-16f) + bias[c1];
        out[(size_t)gw * 64 + c0] = o0;
        out[(size_t)gw * 64 + c1] = o1;
    }
    if (STATS) {
        sV[wid][c0] = valid ? o0 : 0.f;
        sV[wid][c1] = valid ? o1 : 0.f;
        __syncthreads();
        if (tid < 64) {
            float s = 0.f, q = 0.f;
#pragma unroll
            for (int w = 0; w < 8; w++) {
                float v = sV[w][tid];
                s += v;
                q += v * v;
            }
            atomicAdd(&g_stat[tid], s);
            atomicAdd(&g_stat[64 + tid], q);
        }
    }
}

// ---------------- aggregate H=1 C=40 + bias + log_softmax -------------------
__global__ __launch_bounds__(256) void k_agg1_lsm(const float* __restrict__ h,
                                                  const float* __restrict__ bias,
                                                  float* __restrict__ out) {
    int gw = (blockIdx.x * blockDim.x + threadIdx.x) >> 5;
    int lane = threadIdx.x & 31;
    if (gw >= NN) return;
    const int r0 = g_rowptr[gw];
    const int r1 = g_rowptr[gw + 1];
    const int c0 = lane, c1 = lane + 32;
    const bool use1 = lane < 8;

    float ws = __expf(lrelu(g_asrc[gw] + g_adst[gw]));
    float acc0 = ws * h[(size_t)gw * 40 + c0];
    float acc1 = use1 ? ws * h[(size_t)gw * 40 + c1] : 0.f;

    int base = r0;
    for (; base + 8 <= r1; base += 8) {
        int s[8];
#pragma unroll
        for (int j = 0; j < 8; j++) s[j] = g_srcs[base + j];
        float w[8];
#pragma unroll
        for (int j = 0; j < 8; j++) w[j] = g_w[base + j];
        float hv0[8], hv1[8];
#pragma unroll
        for (int j = 0; j < 8; j++) {
            hv0[j] = h[(size_t)s[j] * 40 + c0];
            hv1[j] = use1 ? h[(size_t)s[j] * 40 + c1] : 0.f;
        }
#pragma unroll
        for (int j = 0; j < 8; j++) {
            acc0 += w[j] * hv0[j];
            acc1 += w[j] * hv1[j];
        }
    }
    for (int i = base; i < r1; i++) {
        int s = g_srcs[i];
        float w = g_w[i];
        acc0 += w * h[(size_t)s * 40 + c0];
        if (use1) acc1 += w * h[(size_t)s * 40 + c1];
    }
    float inv = 1.f / (g_sum[gw] + 1e-16f);
    float o0 = acc0 * inv + bias[c0];
    float o1 = use1 ? (acc1 * inv + bias[c1]) : neg_inf();
    float m = fmaxf(o0, o1);
#pragma unroll
    for (int off = 16; off; off >>= 1) m = fmaxf(m, __shfl_xor_sync(0xffffffffu, m, off));
    float se = __expf(o0 - m) + (use1 ? __expf(o1 - m) : 0.f);
#pragma unroll
    for (int off = 16; off; off >>= 1) se += __shfl_xor_sync(0xffffffffu, se, off);
    float ls = __logf(se);
    out[(size_t)gw * 40 + c0] = o0 - m - ls;
    if (use1) out[(size_t)gw * 40 + c1] = o1 - m - ls;
}

// ---------------- BN finalize (restores zero-sum invariant) -----------------
__global__ void k_bnfinal(const float* __restrict__ g, const float* __restrict__ beta) {
    int c = threadIdx.x;
    if (c >= 64) return;
    float mean = g_stat[c] * (1.0f / NN);
    float var = g_stat[64 + c] * (1.0f / NN) - mean * mean;
    float sc = g[c] * rsqrtf(var + 1e-5f);
    g_stat[128 + c] = sc;
    g_stat[192 + c] = beta[c] - mean * sc;
    g_stat[c] = 0.f;
    g_stat[64 + c] = 0.f;
}

// ---------------- launch ----------------------------------------------------
extern "C" void kernel_launch(void* const* d_in, const int* in_sizes, int n_in,
                              void* d_out, int out_size) {
    const float* x   = (const float*)d_in[0];
    const int*   ei  = (const int*)d_in[1];
    const float* W0  = (const float*)d_in[2];
    const float* as0 = (const float*)d_in[3];
    const float* ad0 = (const float*)d_in[4];
    const float* b0  = (const float*)d_in[5];
    const float* g0  = (const float*)d_in[6];
    const float* be0 = (const float*)d_in[7];
    const float* W1  = (const float*)d_in[8];
    const float* as1 = (const float*)d_in[9];
    const float* ad1 = (const float*)d_in[10];
    const float* b1  = (const float*)d_in[11];
    const float* g1  = (const float*)d_in[12];
    const float* be1 = (const float*)d_in[13];
    const float* W2  = (const float*)d_in[14];
    const float* as2 = (const float*)d_in[15];
    const float* ad2 = (const float*)d_in[16];
    const float* b2  = (const float*)d_in[17];
    float* out = (float*)d_out;

    const int gemmGrid = (NN + 63) / 64;
    const int nodeWarpGrid = (NN + 7) / 8;

    k_count<<<(EE + 255) / 256, 256>>>(ei);                            // 1
    k_scan<<<1, 1024>>>();                                             // 2
    k_scatter<<<(EE + 255) / 256, 256>>>(ei);                          // 3

    // ---- layer 0 ----
    k_gemm<128, 64, false, 4><<<gemmGrid, 256>>>(x, W0, g_h, as0, ad0);   // 4 <- profile slot
    k_wgt4<<<nodeWarpGrid, 256>>>();                                   // 5 (zeros cursor)
    k_agg4<true><<<nodeWarpGrid, 256>>>(g_h, b0, g_agg);               // 6
    k_bnfinal<<<1, 64>>>(g0, be0);                                     // 7

    // ---- layer 1 ----
    k_gemm<64, 64, true, 4><<<gemmGrid, 256>>>(g_agg, W1, g_h, as1, ad1); // 8
    k_wgt4<<<nodeWarpGrid, 256>>>();                                   // 9
    k_agg4<true><<<nodeWarpGrid, 256>>>(g_h, b1, g_agg);               // 10
    k_bnfinal<<<1, 64>>>(g1, be1);                                     // 11

    // ---- layer 2 ----
    k_gemm<64, 40, true, 1><<<gemmGrid, 256>>>(g_agg, W2, g_h, as2, ad2); // 12
    k_wgt1<<<nodeWarpGrid, 256>>>();                                   // 13
    k_agg1_lsm<<<nodeWarpGrid, 256>>>(g_h, b2, out);                   // 14
}